// round 12
// baseline (speedup 1.0000x reference)
#include <cuda_runtime.h>

#define RR 256
#define TT 32
#define BB 32
#define YSZ 64

#define TILE 64
#define XS 68      // x tile with halo 2 on each side
#define HS 66      // conv1 output tile (halo 1 for conv2)
#define HSTR 68    // padded stride for 16B-aligned float4 loads
#define CH 2       // channels per hs pass (R10: smaller for 3 CTAs/SM)

#define XS_FLOATS   (XS * XS)          // 4624
#define HS_FLOATS   (HS * HSTR)        // 4488
#define SMEM_FLOATS (XS_FLOATS + CH * HS_FLOATS + 288 + 288 + 32 + 1)
#define SMEM_BYTES  (SMEM_FLOATS * 4)  // 56836

#define S1_GROUP 8
#define S1_SMEM_BYTES (S1_GROUP * TT * YSZ * 4)   // 65536

// 8MB scratch for stage-1 output (device global: no allocation)
__device__ float g_x[BB * RR * RR];

// ---------------------------------------------------------------------------
// Stage 1: x[b,p,q] = sum_t Ht[t,p,q] * yt[b,t,p>>2,q>>2]
// 8 batches per CTA (halves Ht L2 traffic vs 4). Grid: (256, 4).
// ---------------------------------------------------------------------------
__global__ __launch_bounds__(256) void stage1_kernel(
    const float* __restrict__ yt, const float* __restrict__ Ht)
{
    extern __shared__ float s_yt[];      // [S1_GROUP][TT][YSZ] = 64 KB

    const int p   = blockIdx.x;
    const int bg  = blockIdx.y;          // group of 8 batches
    const int tid = threadIdx.x;
    const int yr  = p >> 2;

    for (int i = tid; i < S1_GROUP * TT * YSZ; i += 256) {
        int q4 = i & 63;
        int t  = (i >> 6) & 31;
        int bl = i >> 11;
        s_yt[i] = yt[(((bg * S1_GROUP + bl) * TT + t) * YSZ + yr) * YSZ + q4];
    }
    __syncthreads();

    const int q  = tid;
    const int q4 = q >> 2;
    const float* hp = Ht + p * RR + q;

    float a[S1_GROUP];
#pragma unroll
    for (int bl = 0; bl < S1_GROUP; bl++) a[bl] = 0.f;

#pragma unroll
    for (int t = 0; t < TT; t++) {
        float h = hp[t * RR * RR];
#pragma unroll
        for (int bl = 0; bl < S1_GROUP; bl++)
            a[bl] = fmaf(h, s_yt[(bl * TT + t) * YSZ + q4], a[bl]);
    }
    float* xp = g_x + (bg * S1_GROUP) * RR * RR + p * RR + q;
#pragma unroll
    for (int bl = 0; bl < S1_GROUP; bl++)
        xp[bl * RR * RR] = a[bl];
}

// ---------------------------------------------------------------------------
// Conv(1->32,3x3) -> ReLU -> Conv(32->1,3x3), fused, CH=2 per pass.
// conv1: 6-row vertical sliding walks (3 LDS/point). conv2: 4x4 reg tile.
// Grid: (4, 4, 32). 256 threads. 56.8 KB dyn smem -> 3 CTAs/SM.
// ---------------------------------------------------------------------------
__global__ __launch_bounds__(256, 3) void conv_fused_kernel(
    const float* __restrict__ W1, const float* __restrict__ b1,
    const float* __restrict__ W2, const float* __restrict__ b2,
    float* __restrict__ out)
{
    extern __shared__ float smem[];
    float* xs  = smem;                        // 68x68
    float* hsb = smem + XS_FLOATS;            // CH * 66x68
    float* w1s = hsb + CH * HS_FLOATS;        // 288
    float* w2s = w1s + 288;                   // 288
    float* b1s = w2s + 288;                   // 32
    float* b2s = b1s + 32;                    // 1

    const int b   = blockIdx.z;
    const int ty0 = blockIdx.y * TILE;
    const int tx0 = blockIdx.x * TILE;
    const int tid = threadIdx.x;

    for (int i = tid; i < 288; i += 256) { w1s[i] = W1[i]; w2s[i] = W2[i]; }
    if (tid < 32)  b1s[tid] = b1[tid];
    if (tid == 0)  b2s[0] = b2[0];

    // Load x tile with halo 2 (zero-pad at image borders)
    const float* xb = g_x + b * RR * RR;
    for (int i = tid; i < XS_FLOATS; i += 256) {
        int ry = i / XS, rx = i - ry * XS;
        int gy = ty0 - 2 + ry, gx = tx0 - 2 + rx;
        float v = 0.f;
        if (gy >= 0 && gy < RR && gx >= 0 && gx < RR) v = xb[gy * RR + gx];
        xs[i] = v;
    }
    __syncthreads();

    const int tx = tid & 15;
    const int ty = tid >> 4;
    const int ox = tx * 4;
    const int oy = ty * 4;

    float acc[4][4];
#pragma unroll
    for (int i = 0; i < 4; i++)
#pragma unroll
        for (int j = 0; j < 4; j++) acc[i][j] = 0.f;

    for (int g = 0; g < 32 / CH; g++) {
        const int c0 = g * CH;

        float w1r[CH][9], bcr[CH];
#pragma unroll
        for (int cc = 0; cc < CH; cc++) {
#pragma unroll
            for (int k = 0; k < 9; k++) w1r[cc][k] = w1s[(c0 + cc) * 9 + k];
            bcr[cc] = b1s[c0 + cc];
        }

        // --- conv1: 11 bands x 66 cols of 6-row vertical sliding walks ---
        for (int s = tid; s < 11 * 66; s += 256) {
            int band = s / 66;
            int col  = s - band * 66;
            int r0   = band * 6;
            bool col_oob = ((unsigned)(tx0 + col - 1) >= RR);
            const float* xp = xs + r0 * XS + col;
            float* hp = hsb + r0 * HSTR + col;

            float x0 = xp[0],  x1 = xp[1],      x2 = xp[2];
            float x3 = xp[XS], x4 = xp[XS + 1], x5 = xp[XS + 2];
            xp += 2 * XS;

            int gy = ty0 + r0 - 1;
#pragma unroll
            for (int r = 0; r < 6; r++) {
                float x6 = xp[0], x7 = xp[1], x8 = xp[2];
                bool oob = col_oob || ((unsigned)gy >= RR);
#pragma unroll
                for (int cc = 0; cc < CH; cc++) {
                    float v = bcr[cc];
                    v = fmaf(w1r[cc][0], x0, v);
                    v = fmaf(w1r[cc][1], x1, v);
                    v = fmaf(w1r[cc][2], x2, v);
                    v = fmaf(w1r[cc][3], x3, v);
                    v = fmaf(w1r[cc][4], x4, v);
                    v = fmaf(w1r[cc][5], x5, v);
                    v = fmaf(w1r[cc][6], x6, v);
                    v = fmaf(w1r[cc][7], x7, v);
                    v = fmaf(w1r[cc][8], x8, v);
                    float rr = fmaxf(v, 0.f);
                    if (oob) rr = 0.f;
                    hp[cc * HS_FLOATS] = rr;
                }
                hp += HSTR; xp += XS; gy++;
                x0 = x3; x1 = x4; x2 = x5;
                x3 = x6; x4 = x7; x5 = x8;
            }
        }
        __syncthreads();

        // --- conv2: accumulate CH channels into 4x4 register tile ---
#pragma unroll
        for (int cc = 0; cc < CH; cc++) {
            float w2r[9];
#pragma unroll
            for (int k = 0; k < 9; k++) w2r[k] = w2s[(c0 + cc) * 9 + k];
            const float* hc = hsb + cc * HS_FLOATS;
#pragma unroll
            for (int pr = 0; pr < 6; pr++) {
                const float* hq = hc + (oy + pr) * HSTR + ox;
                float4 v4 = *(const float4*)hq;
                float2 v2 = *(const float2*)(hq + 4);
                float rv[6] = { v4.x, v4.y, v4.z, v4.w, v2.x, v2.y };
#pragma unroll
                for (int i = 0; i < 4; i++) {
                    int dy = pr - i;
                    if (dy >= 0 && dy < 3) {
#pragma unroll
                        for (int j = 0; j < 4; j++) {
                            acc[i][j] = fmaf(w2r[dy * 3 + 0], rv[j],     acc[i][j]);
                            acc[i][j] = fmaf(w2r[dy * 3 + 1], rv[j + 1], acc[i][j]);
                            acc[i][j] = fmaf(w2r[dy * 3 + 2], rv[j + 2], acc[i][j]);
                        }
                    }
                }
            }
        }
        __syncthreads();   // protect hs before next group overwrites it
    }

    float bb = b2s[0];
#pragma unroll
    for (int i = 0; i < 4; i++) {
        float4 o;
        o.x = acc[i][0] + bb;
        o.y = acc[i][1] + bb;
        o.z = acc[i][2] + bb;
        o.w = acc[i][3] + bb;
        *(float4*)(out + (size_t)(b * RR + ty0 + oy + i) * RR + tx0 + ox) = o;
    }
}

extern "C" void kernel_launch(void* const* d_in, const int* in_sizes, int n_in,
                              void* d_out, int out_size) {
    const float* yt = (const float*)d_in[0];
    const float* Ht = (const float*)d_in[1];
    const float* W1 = (const float*)d_in[2];
    const float* b1 = (const float*)d_in[3];
    const float* W2 = (const float*)d_in[4];
    const float* b2 = (const float*)d_in[5];
    float* out = (float*)d_out;

    // Immediate (non-stream) API: executes at call time, not captured.
    cudaFuncSetAttribute(stage1_kernel,
                         cudaFuncAttributeMaxDynamicSharedMemorySize, S1_SMEM_BYTES);
    cudaFuncSetAttribute(conv_fused_kernel,
                         cudaFuncAttributeMaxDynamicSharedMemorySize, SMEM_BYTES);

    stage1_kernel<<<dim3(256, BB / S1_GROUP), 256, S1_SMEM_BYTES>>>(yt, Ht);
    conv_fused_kernel<<<dim3(4, 4, 32), 256, SMEM_BYTES>>>(W1, b1, W2, b2, out);
}